// round 15
// baseline (speedup 1.0000x reference)
#include <cuda_runtime.h>
#include <cuda_fp16.h>
#include <cstdint>

#define E_DIM 288
#define B_SZ 4
#define N_SEQ 2048
#define H_NUM 8
#define D_HEAD 36
#define M_ROWS (B_SZ * N_SEQ)  // 8192

__device__ float g_q[M_ROWS * E_DIM];
__device__ float g_k[M_ROWS * E_DIM];
__device__ float g_v[M_ROWS * E_DIM];
__device__ float g_att[M_ROWS * E_DIM];

// ============================ helpers ============================
__device__ __forceinline__ uint32_t f2tf(float x) {
  uint32_t u;
  asm("cvt.rna.tf32.f32 %0, %1;" : "=r"(u) : "f"(x));
  return u;
}
__device__ __forceinline__ uint32_t h2(float lo, float hi) {
  __half2 h = __floats2half2_rn(lo, hi);
  return *(uint32_t*)&h;
}
__device__ __forceinline__ void mma8(float* c, uint32_t a0, uint32_t a1,
                                     uint32_t a2, uint32_t a3, uint32_t b0,
                                     uint32_t b1) {
  asm volatile(
      "mma.sync.aligned.m16n8k8.row.col.f32.tf32.tf32.f32 "
      "{%0,%1,%2,%3}, {%4,%5,%6,%7}, {%8,%9}, {%0,%1,%2,%3};"
      : "+f"(c[0]), "+f"(c[1]), "+f"(c[2]), "+f"(c[3])
      : "r"(a0), "r"(a1), "r"(a2), "r"(a3), "r"(b0), "r"(b1));
}
__device__ __forceinline__ void mma16(float* c, uint32_t a0, uint32_t a1,
                                      uint32_t a2, uint32_t a3, uint32_t b0,
                                      uint32_t b1) {
  asm volatile(
      "mma.sync.aligned.m16n8k16.row.col.f32.f16.f16.f32 "
      "{%0,%1,%2,%3}, {%4,%5,%6,%7}, {%8,%9}, {%0,%1,%2,%3};"
      : "+f"(c[0]), "+f"(c[1]), "+f"(c[2]), "+f"(c[3])
      : "r"(a0), "r"(a1), "r"(a2), "r"(a3), "r"(b0), "r"(b1));
}
#define CP_ASYNC16(dst32, src) \
  asm volatile("cp.async.cg.shared.global [%0], [%1], 16;" :: "r"(dst32), "l"(src))
#define CP_COMMIT() asm volatile("cp.async.commit_group;" ::: "memory")
#define CP_WAIT(n) asm volatile("cp.async.wait_group %0;" :: "n"(n) : "memory")

// ---------------------------------------------------------------------------
// fp16 HMMA flash attention, R15:
//  - Q/K/V/P in fp16 (same 10-bit mantissa as tf32 -> same accuracy),
//    fp32 accumulators. m16n8k16: QK = 3 k-steps, PV A-frag = packed exp(S).
//  - K half2 d-pairs [24][72] (bank 8q+rg: conflict-free reads);
//    V half2 key-pairs [32][40] (bank 8q+8v+rg: conflict-free reads).
//  - double-buffer + register prefetch (R13 structure).
// ---------------------------------------------------------------------------
__global__ __launch_bounds__(256, 2) void attn_mma_kernel(
    const float* __restrict__ Q, const float* __restrict__ K,
    const float* __restrict__ V, float* __restrict__ Oa) {
  __shared__ uint32_t Kt2[2][24 * 72];  // [buf][dpair*72 + key]
  __shared__ uint32_t Vh[2][32 * 40];   // [buf][keypair*40 + d]

  const int t = threadIdx.x;
  const int wid = t >> 5;
  const int lane = t & 31;
  const int q = lane & 3;
  const int rg = lane >> 2;
  const int b = blockIdx.y >> 3, h = blockIdx.y & 7;
  const int q0 = blockIdx.x * 128;

  // zero K d-pairs 18..23 (d=36..47)
  for (int i = t; i < 2 * 6 * 72; i += 256) {
    int bu = i / 432, r = i - bu * 432;
    Kt2[bu][18 * 72 + r] = 0;
  }
  // zero V dims 36..39 (all 32 key-pairs)
  for (int i = t; i < 2 * 128; i += 256) {
    int bu = i >> 7, r = i & 127;
    int p = r >> 2, c = r & 3;
    Vh[bu][p * 40 + 36 + c] = 0;
  }

  // ---- Q fragments (fp16 half2, registers) ----
  const float* qg = Q + ((size_t)(b * N_SEQ + q0 + wid * 16)) * E_DIM + h * D_HEAD;
  uint32_t qh[3][4];
#pragma unroll
  for (int s = 0; s < 3; s++) {
    int k0 = 16 * s;
#pragma unroll
    for (int half = 0; half < 2; half++) {  // a0/a1 (cols k0+2q) ; a2/a3 (+8)
      int d0 = k0 + half * 8 + 2 * q;
      int d1 = d0 + 1;
      float v00 = (d0 < 36) ? qg[(size_t)rg * E_DIM + d0] : 0.f;
      float v01 = (d1 < 36) ? qg[(size_t)rg * E_DIM + d1] : 0.f;
      float v10 = (d0 < 36) ? qg[(size_t)(rg + 8) * E_DIM + d0] : 0.f;
      float v11 = (d1 < 36) ? qg[(size_t)(rg + 8) * E_DIM + d1] : 0.f;
      qh[s][half * 2 + 0] = h2(v00, v01);
      qh[s][half * 2 + 1] = h2(v10, v11);
    }
  }

  // ---- per-thread load slots: 576 float4 over 256 threads ----
  int goff[3], koff[3], jkey[3], vbase16[3];
  bool act[3];
#pragma unroll
  for (int it = 0; it < 3; it++) {
    int idx = t + (it << 8);
    act[it] = idx < 576;
    int j = idx / 9;
    if (j > 63) j = 63;
    int f4 = idx - j * 9;
    goff[it] = j * E_DIM + f4 * 4;
    koff[it] = (2 * f4) * 72 + j;  // +72 for the second d-pair
    jkey[it] = j;
    // u16 index into Vh: ((j>>1)*40 + d)*2 + (j&1), d = 4*f4..
    vbase16[it] = ((j >> 1) * 40 + 4 * f4) * 2 + (j & 1);
  }
  const float* kg = K + ((size_t)(b * N_SEQ)) * E_DIM + h * D_HEAD;
  const float* vg = V + ((size_t)(b * N_SEQ)) * E_DIM + h * D_HEAD;

  float O[5][4];
#pragma unroll
  for (int v = 0; v < 5; v++)
#pragma unroll
    for (int i = 0; i < 4; i++) O[v][i] = 0.f;
  float l0 = 0.f, l1 = 0.f;

  float4 kr[3], vr[3];
#pragma unroll
  for (int it = 0; it < 3; it++)
    if (act[it]) {
      kr[it] = *(const float4*)(kg + goff[it]);
      vr[it] = *(const float4*)(vg + goff[it]);
    }
#pragma unroll
  for (int it = 0; it < 3; it++)
    if (act[it]) {
      Kt2[0][koff[it]] = h2(kr[it].x, kr[it].y);
      Kt2[0][koff[it] + 72] = h2(kr[it].z, kr[it].w);
      uint16_t* vd = (uint16_t*)&Vh[0][0];
      vd[vbase16[it] + 0] = __half_as_ushort(__float2half_rn(vr[it].x));
      vd[vbase16[it] + 2] = __half_as_ushort(__float2half_rn(vr[it].y));
      vd[vbase16[it] + 4] = __half_as_ushort(__float2half_rn(vr[it].z));
      vd[vbase16[it] + 6] = __half_as_ushort(__float2half_rn(vr[it].w));
    }
  __syncthreads();

  for (int kt = 0; kt < N_SEQ / 64; kt++) {
    const int buf = kt & 1;
    if (kt < N_SEQ / 64 - 1) {
      const float* kp = kg + (size_t)(kt + 1) * 64 * E_DIM;
      const float* vp = vg + (size_t)(kt + 1) * 64 * E_DIM;
#pragma unroll
      for (int it = 0; it < 3; it++)
        if (act[it]) {
          kr[it] = *(const float4*)(kp + goff[it]);
          vr[it] = *(const float4*)(vp + goff[it]);
        }
    }

    const uint32_t* Kb = &Kt2[buf][0];
    const uint32_t* Vb = &Vh[buf][0];
#pragma unroll
    for (int np = 0; np < 4; np++) {
      const int col0 = 16 * np + rg;      // key col for chain 0 (n=2np)
      const int col1 = 16 * np + 8 + rg;  // chain 1 (n=2np+1)
      float S0[4] = {0.f, 0.f, 0.f, 0.f};
      float S1[4] = {0.f, 0.f, 0.f, 0.f};
#pragma unroll
      for (int s = 0; s < 3; s++) {
        const uint32_t* kp0 = Kb + (8 * s + q) * 72;
        const uint32_t* kp1 = Kb + (8 * s + 4 + q) * 72;
        mma16(S0, qh[s][0], qh[s][1], qh[s][2], qh[s][3], kp0[col0], kp1[col0]);
        mma16(S1, qh[s][0], qh[s][1], qh[s][2], qh[s][3], kp0[col1], kp1[col1]);
      }
      float p00 = __expf(S0[0]);
      float p01 = __expf(S0[1]);
      float p02 = __expf(S0[2]);
      float p03 = __expf(S0[3]);
      float p10 = __expf(S1[0]);
      float p11 = __expf(S1[1]);
      float p12 = __expf(S1[2]);
      float p13 = __expf(S1[3]);
      l0 += p00 + p01 + p10 + p11;
      l1 += p02 + p03 + p12 + p13;
      uint32_t pa0 = h2(p00, p01);
      uint32_t pa1 = h2(p02, p03);
      uint32_t pa2 = h2(p10, p11);
      uint32_t pa3 = h2(p12, p13);
      const uint32_t* vp0 = Vb + (8 * np + q) * 40 + rg;
      const uint32_t* vp1 = Vb + (8 * np + 4 + q) * 40 + rg;
#pragma unroll
      for (int v = 0; v < 5; v++) {
        mma16(O[v], pa0, pa1, pa2, pa3, vp0[8 * v], vp1[8 * v]);
      }
    }

    if (kt < N_SEQ / 64 - 1) {
      uint32_t* kd = &Kt2[buf ^ 1][0];
      uint16_t* vd = (uint16_t*)&Vh[buf ^ 1][0];
#pragma unroll
      for (int it = 0; it < 3; it++)
        if (act[it]) {
          kd[koff[it]] = h2(kr[it].x, kr[it].y);
          kd[koff[it] + 72] = h2(kr[it].z, kr[it].w);
          vd[vbase16[it] + 0] = __half_as_ushort(__float2half_rn(vr[it].x));
          vd[vbase16[it] + 2] = __half_as_ushort(__float2half_rn(vr[it].y));
          vd[vbase16[it] + 4] = __half_as_ushort(__float2half_rn(vr[it].z));
          vd[vbase16[it] + 6] = __half_as_ushort(__float2half_rn(vr[it].w));
        }
    }
    __syncthreads();
  }

  l0 += __shfl_xor_sync(0xffffffffu, l0, 1);
  l0 += __shfl_xor_sync(0xffffffffu, l0, 2);
  l1 += __shfl_xor_sync(0xffffffffu, l1, 1);
  l1 += __shfl_xor_sync(0xffffffffu, l1, 2);
  float inv0 = 1.f / l0, inv1 = 1.f / l1;

  const int row = q0 + wid * 16 + rg;
  float* ob0 = Oa + (size_t)(b * N_SEQ + row) * E_DIM + h * D_HEAD;
  float* ob1 = Oa + (size_t)(b * N_SEQ + row + 8) * E_DIM + h * D_HEAD;
#pragma unroll
  for (int v = 0; v < 5; v++) {
    int col = 8 * v + 2 * q;
    if (col < 36) {
      *(float2*)(ob0 + col) = make_float2(O[v][0] * inv0, O[v][1] * inv0);
      *(float2*)(ob1 + col) = make_float2(O[v][2] * inv1, O[v][3] * inv1);
    }
  }
}

// ---------------------------------------------------------------------------
// GEMM body (unchanged from R13): single-term tf32, 3-stage cp.async pipeline.
// ---------------------------------------------------------------------------
#define NKT (E_DIM / 16)  // 18

__device__ __forceinline__ void gemm_body(const float* __restrict__ A,
                                          const float* __restrict__ W,
                                          const float* __restrict__ bias,
                                          float* __restrict__ C, float scale,
                                          int row_blk, int col_blk) {
  __shared__ float Wsm[3][16][104];
  __shared__ float As[3][64][20];

  const int t = threadIdx.x;
  const int wid = t >> 5;
  const int lane = t & 31;
  const int q = lane & 3;
  const int rg = lane >> 2;
  const int warp_m = wid & 1;
  const int warp_n = wid >> 1;
  const int ncol0 = warp_n * 48;

  int wg_off[3], ws_off[3];
#pragma unroll
  for (int i = 0; i < 3; i++) {
    int idx = t + i * 128;
    int kk = idx / 24, n4 = idx - kk * 24;
    wg_off[i] = kk * E_DIM + n4 * 4;
    ws_off[i] = kk * 104 + n4 * 4;
  }
  int ag_off[2], as_off[2];
#pragma unroll
  for (int i = 0; i < 2; i++) {
    int idx = t + i * 128;
    int row = idx >> 2, k4 = idx & 3;
    ag_off[i] = row * E_DIM + k4 * 4;
    as_off[i] = row * 20 + k4 * 4;
  }
  const float* Wg = W + col_blk;
  const float* Ag = A + (size_t)row_blk * E_DIM;
  const uint32_t wbase = (uint32_t)__cvta_generic_to_shared(&Wsm[0][0][0]);
  const uint32_t abase = (uint32_t)__cvta_generic_to_shared(&As[0][0][0]);

  float acc[2][6][4];
#pragma unroll
  for (int mb = 0; mb < 2; mb++)
#pragma unroll
    for (int nb = 0; nb < 6; nb++)
#pragma unroll
      for (int i = 0; i < 4; i++) acc[mb][nb][i] = 0.f;

#pragma unroll
  for (int st = 0; st < 3; st++) {
    const int k0 = st * 16;
#pragma unroll
    for (int i = 0; i < 3; i++)
      CP_ASYNC16(wbase + (uint32_t)(st * 16 * 104 + ws_off[i]) * 4u,
                 Wg + (size_t)k0 * E_DIM + wg_off[i]);
#pragma unroll
    for (int i = 0; i < 2; i++)
      CP_ASYNC16(abase + (uint32_t)(st * 64 * 20 + as_off[i]) * 4u,
                 Ag + k0 + ag_off[i]);
    CP_COMMIT();
  }

  for (int kt = 0; kt < NKT; kt++) {
    if (kt < NKT - 2) {
      CP_WAIT(2);
    } else if (kt == NKT - 2) {
      CP_WAIT(1);
    } else {
      CP_WAIT(0);
    }
    __syncthreads();

    const int buf = kt % 3;
    const float* Wb = &Wsm[buf][0][0];
    const float* Ab = &As[buf][0][0];
#pragma unroll
    for (int s = 0; s < 2; s++) {
      uint32_t ah[2][4];
#pragma unroll
      for (int mb = 0; mb < 2; mb++) {
        const int r0 = warp_m * 32 + mb * 16;
        ah[mb][0] = f2tf(Ab[(r0 + rg) * 20 + 8 * s + q]);
        ah[mb][1] = f2tf(Ab[(r0 + rg + 8) * 20 + 8 * s + q]);
        ah[mb][2] = f2tf(Ab[(r0 + rg) * 20 + 8 * s + q + 4]);
        ah[mb][3] = f2tf(Ab[(r0 + rg + 8) * 20 + 8 * s + q + 4]);
      }
#pragma unroll
      for (int nb = 0; nb < 6; nb++) {
        const int n = ncol0 + nb * 8 + rg;
        uint32_t bh0 = f2tf(Wb[(8 * s + q) * 104 + n]);
        uint32_t bh1 = f2tf(Wb[(8 * s + q + 4) * 104 + n]);
#pragma unroll
        for (int mb = 0; mb < 2; mb++) {
          mma8(acc[mb][nb], ah[mb][0], ah[mb][1], ah[mb][2], ah[mb][3], bh0, bh1);
        }
      }
    }
    __syncthreads();

    if (kt + 3 < NKT) {
      const int k0 = (kt + 3) * 16;
#pragma unroll
      for (int i = 0; i < 3; i++)
        CP_ASYNC16(wbase + (uint32_t)(buf * 16 * 104 + ws_off[i]) * 4u,
                   Wg + (size_t)k0 * E_DIM + wg_off[i]);
#pragma unroll
      for (int i = 0; i < 2; i++)
        CP_ASYNC16(abase + (uint32_t)(buf * 64 * 20 + as_off[i]) * 4u,
                   Ag + k0 + ag_off[i]);
      CP_COMMIT();
    }
  }

#pragma unroll
  for (int mb = 0; mb < 2; mb++) {
    const int r0 = row_blk + warp_m * 32 + mb * 16 + rg;
#pragma unroll
    for (int nb = 0; nb < 6; nb++) {
      const int c = col_blk + ncol0 + nb * 8 + 2 * q;
      const float b0 = bias[c], b1 = bias[c + 1];
      *(float2*)(C + (size_t)r0 * E_DIM + c) =
          make_float2((acc[mb][nb][0] + b0) * scale,
                      (acc[mb][nb][1] + b1) * scale);
      *(float2*)(C + (size_t)(r0 + 8) * E_DIM + c) =
          make_float2((acc[mb][nb][2] + b0) * scale,
                      (acc[mb][nb][3] + b1) * scale);
    }
  }
}

__global__ __launch_bounds__(128, 6) void gemm_qkv_kernel(
    const float* __restrict__ Aq, const float* __restrict__ Ak,
    const float* __restrict__ Av, const float* __restrict__ Wq,
    const float* __restrict__ Wk, const float* __restrict__ Wv,
    const float* __restrict__ bq, const float* __restrict__ bk,
    const float* __restrict__ bv, float* __restrict__ Cq,
    float* __restrict__ Ck, float* __restrict__ Cv, float scaling) {
  const int z = blockIdx.z;
  const float* A = (z == 0) ? Aq : (z == 1) ? Ak : Av;
  const float* W = (z == 0) ? Wq : (z == 1) ? Wk : Wv;
  const float* bias = (z == 0) ? bq : (z == 1) ? bk : bv;
  float* C = (z == 0) ? Cq : (z == 1) ? Ck : Cv;
  const float scale = (z == 0) ? scaling : 1.0f;
  gemm_body(A, W, bias, C, scale, blockIdx.y * 64, blockIdx.x * 96);
}

__global__ __launch_bounds__(128, 6) void gemm_mma_kernel(
    const float* __restrict__ A, const float* __restrict__ W,
    const float* __restrict__ bias, float* __restrict__ C, float scale) {
  gemm_body(A, W, bias, C, scale, blockIdx.y * 64, blockIdx.x * 96);
}

// ---------------------------------------------------------------------------
extern "C" void kernel_launch(void* const* d_in, const int* in_sizes, int n_in,
                              void* d_out, int out_size) {
  const float* query = (const float*)d_in[0];
  const float* key   = (const float*)d_in[1];
  const float* value = (const float*)d_in[2];
  const float* Wq = (const float*)d_in[3];
  const float* bq = (const float*)d_in[4];
  const float* Wk = (const float*)d_in[5];
  const float* bk = (const float*)d_in[6];
  const float* Wv = (const float*)d_in[7];
  const float* bv = (const float*)d_in[8];
  const float* Wo = (const float*)d_in[9];
  const float* bo = (const float*)d_in[10];
  float* out = (float*)d_out;

  float *gq, *gk, *gv, *ga;
  cudaGetSymbolAddress((void**)&gq, g_q);
  cudaGetSymbolAddress((void**)&gk, g_k);
  cudaGetSymbolAddress((void**)&gv, g_v);
  cudaGetSymbolAddress((void**)&ga, g_att);

  const float scaling = 1.0f / 6.0f;  // D=36 -> 36^-0.5
  dim3 qkvGrid(E_DIM / 96, M_ROWS / 64, 3);
  dim3 gGrid(E_DIM / 96, M_ROWS / 64);
  dim3 gBlk(128);

  gemm_qkv_kernel<<<qkvGrid, gBlk>>>(query, key, value, Wq, Wk, Wv, bq, bk, bv,
                                     gq, gk, gv, scaling);

  attn_mma_kernel<<<dim3(N_SEQ / 128, B_SZ * H_NUM), 256>>>(gq, gk, gv, ga);

  gemm_mma_kernel<<<gGrid, gBlk>>>(ga, Wo, bo, out, 1.0f);
}

// round 17
// speedup vs baseline: 1.1486x; 1.1486x over previous
#include <cuda_runtime.h>
#include <cuda_fp16.h>
#include <cstdint>

#define E_DIM 288
#define B_SZ 4
#define N_SEQ 2048
#define H_NUM 8
#define D_HEAD 36
#define M_ROWS (B_SZ * N_SEQ)  // 8192

__device__ float g_q[M_ROWS * E_DIM];
__device__ float g_k[M_ROWS * E_DIM];
__device__ float g_v[M_ROWS * E_DIM];
__device__ float g_att[M_ROWS * E_DIM];

// ============================ helpers ============================
__device__ __forceinline__ uint32_t f2tf(float x) {
  uint32_t u;
  asm("cvt.rna.tf32.f32 %0, %1;" : "=r"(u) : "f"(x));
  return u;
}
__device__ __forceinline__ uint32_t h2(float lo, float hi) {
  __half2 h = __floats2half2_rn(lo, hi);
  return *(uint32_t*)&h;
}
__device__ __forceinline__ void mma8(float* c, uint32_t a0, uint32_t a1,
                                     uint32_t a2, uint32_t a3, uint32_t b0,
                                     uint32_t b1) {
  asm volatile(
      "mma.sync.aligned.m16n8k8.row.col.f32.tf32.tf32.f32 "
      "{%0,%1,%2,%3}, {%4,%5,%6,%7}, {%8,%9}, {%0,%1,%2,%3};"
      : "+f"(c[0]), "+f"(c[1]), "+f"(c[2]), "+f"(c[3])
      : "r"(a0), "r"(a1), "r"(a2), "r"(a3), "r"(b0), "r"(b1));
}
__device__ __forceinline__ void mma16(float* c, uint32_t a0, uint32_t a1,
                                      uint32_t a2, uint32_t a3, uint32_t b0,
                                      uint32_t b1) {
  asm volatile(
      "mma.sync.aligned.m16n8k16.row.col.f32.f16.f16.f32 "
      "{%0,%1,%2,%3}, {%4,%5,%6,%7}, {%8,%9}, {%0,%1,%2,%3};"
      : "+f"(c[0]), "+f"(c[1]), "+f"(c[2]), "+f"(c[3])
      : "r"(a0), "r"(a1), "r"(a2), "r"(a3), "r"(b0), "r"(b1));
}
#define CP_ASYNC16(dst32, src) \
  asm volatile("cp.async.cg.shared.global [%0], [%1], 16;" :: "r"(dst32), "l"(src))
#define CP_COMMIT() asm volatile("cp.async.commit_group;" ::: "memory")
#define CP_WAIT(n) asm volatile("cp.async.wait_group %0;" :: "n"(n) : "memory")

// ---------------------------------------------------------------------------
// fp16 HMMA flash attention, R17 (= R16 with V store stride FIXED):
//  u16 layout:  K[16*(s*72+key) + 4q + 2c + par] = K[d=16s+8c+2q+par][key]
//               V[16*(np*40+d)  + 4q + 2c + par] = V[key=16np+8c+2q+par][d]
//  Every mma16 B-fragment (b0,b1) = one aligned LDS.64, conflict-free.
//  V per-d u16 stride is 16 (NOT 8 — R16's NaN bug).
// ---------------------------------------------------------------------------
__global__ __launch_bounds__(256, 2) void attn_mma_kernel(
    const float* __restrict__ Q, const float* __restrict__ K,
    const float* __restrict__ V, float* __restrict__ Oa) {
  __shared__ uint32_t Ks[2][1728];  // ((s*72+key)*4+q)*2+c
  __shared__ uint32_t Vs[2][1280];  // ((np*40+d)*4+q)*2+c

  const int t = threadIdx.x;
  const int wid = t >> 5;
  const int lane = t & 31;
  const int q = lane & 3;
  const int rg = lane >> 2;
  const int b = blockIdx.y >> 3, h = blockIdx.y & 7;
  const int q0 = blockIdx.x * 128;

  // zero K s=2 block (d=32..47; only d=32..35 slots are ever stored)
  for (int i = t; i < 2 * 576; i += 256) {
    int bu = i / 576, r = i - bu * 576;
    Ks[bu][1152 + r] = 0;
  }
  // zero V d=36..39 (never stored)
  for (int i = t; i < 2 * 128; i += 256) {
    int bu = i >> 7, r = i & 127;  // r = np*32 + dd*8 + (q*2+c)
    int np = r >> 5, rr = r & 31;
    int dd = rr >> 3, qc = rr & 7;
    Vs[bu][(np * 40 + 36 + dd) * 8 + qc] = 0;
  }

  // ---- Q fragments (fp16 half2, registers) ----
  const float* qg = Q + ((size_t)(b * N_SEQ + q0 + wid * 16)) * E_DIM + h * D_HEAD;
  uint32_t qh[3][4];
#pragma unroll
  for (int s = 0; s < 3; s++) {
    int k0 = 16 * s;
#pragma unroll
    for (int half = 0; half < 2; half++) {
      int d0 = k0 + half * 8 + 2 * q;
      int d1 = d0 + 1;
      float v00 = (d0 < 36) ? qg[(size_t)rg * E_DIM + d0] : 0.f;
      float v01 = (d1 < 36) ? qg[(size_t)rg * E_DIM + d1] : 0.f;
      float v10 = (d0 < 36) ? qg[(size_t)(rg + 8) * E_DIM + d0] : 0.f;
      float v11 = (d1 < 36) ? qg[(size_t)(rg + 8) * E_DIM + d1] : 0.f;
      qh[s][half * 2 + 0] = h2(v00, v01);
      qh[s][half * 2 + 1] = h2(v10, v11);
    }
  }

  // ---- per-thread load slots: 576 float4 over 256 threads ----
  int goff[3], koff0[3], koff1[3], v16[3];
  bool act[3];
#pragma unroll
  for (int it = 0; it < 3; it++) {
    int idx = t + (it << 8);
    act[it] = idx < 576;
    int j = idx / 9;
    if (j > 63) j = 63;
    int f4 = idx - j * 9;
    goff[it] = j * E_DIM + f4 * 4;
    // K: d-pairs dp0=2*f4 (d=4f4,4f4+1), dp1=2*f4+1 (d=4f4+2,4f4+3)
    int dp0 = 2 * f4;
    int s0 = dp0 >> 3, w0 = dp0 & 7;
    koff0[it] = ((s0 * 72 + j) * 4 + (w0 & 3)) * 2 + (w0 >> 2);
    int dp1 = dp0 + 1;
    int s1 = dp1 >> 3, w1 = dp1 & 7;
    koff1[it] = ((s1 * 72 + j) * 4 + (w1 & 3)) * 2 + (w1 >> 2);
    // V: key j = 16np + 8c + 2qv + par; u16 = 16*(np*40+d) + 4qv + 2c + par
    int np = j >> 4, jj = j & 15;
    int c = jj >> 3, r7 = jj & 7;
    int qv = r7 >> 1, par = r7 & 1;
    v16[it] = 16 * (np * 40 + 4 * f4) + 4 * qv + 2 * c + par;
  }
  const float* kg = K + ((size_t)(b * N_SEQ)) * E_DIM + h * D_HEAD;
  const float* vg = V + ((size_t)(b * N_SEQ)) * E_DIM + h * D_HEAD;

  float O[5][4];
#pragma unroll
  for (int v = 0; v < 5; v++)
#pragma unroll
    for (int i = 0; i < 4; i++) O[v][i] = 0.f;
  float l0 = 0.f, l1 = 0.f;

  float4 kr[3], vr[3];
#pragma unroll
  for (int it = 0; it < 3; it++)
    if (act[it]) {
      kr[it] = *(const float4*)(kg + goff[it]);
      vr[it] = *(const float4*)(vg + goff[it]);
    }
#pragma unroll
  for (int it = 0; it < 3; it++)
    if (act[it]) {
      Ks[0][koff0[it]] = h2(kr[it].x, kr[it].y);
      Ks[0][koff1[it]] = h2(kr[it].z, kr[it].w);
      uint16_t* vd = (uint16_t*)&Vs[0][0];
      vd[v16[it] + 0] = __half_as_ushort(__float2half_rn(vr[it].x));
      vd[v16[it] + 16] = __half_as_ushort(__float2half_rn(vr[it].y));
      vd[v16[it] + 32] = __half_as_ushort(__float2half_rn(vr[it].z));
      vd[v16[it] + 48] = __half_as_ushort(__float2half_rn(vr[it].w));
    }
  __syncthreads();

  for (int kt = 0; kt < N_SEQ / 64; kt++) {
    const int buf = kt & 1;
    if (kt < N_SEQ / 64 - 1) {
      const float* kp = kg + (size_t)(kt + 1) * 64 * E_DIM;
      const float* vp = vg + (size_t)(kt + 1) * 64 * E_DIM;
#pragma unroll
      for (int it = 0; it < 3; it++)
        if (act[it]) {
          kr[it] = *(const float4*)(kp + goff[it]);
          vr[it] = *(const float4*)(vp + goff[it]);
        }
    }

    const uint32_t* Kb = &Ks[buf][0];
    const uint32_t* Vb = &Vs[buf][0];
#pragma unroll
    for (int np = 0; np < 4; np++) {
      float S0[4] = {0.f, 0.f, 0.f, 0.f};
      float S1[4] = {0.f, 0.f, 0.f, 0.f};
      const int key0 = 16 * np + rg;      // chain 0
      const int key1 = 16 * np + 8 + rg;  // chain 1
#pragma unroll
      for (int s = 0; s < 3; s++) {
        uint2 x0 = *(const uint2*)(Kb + ((s * 72 + key0) * 4 + q) * 2);
        uint2 x1 = *(const uint2*)(Kb + ((s * 72 + key1) * 4 + q) * 2);
        mma16(S0, qh[s][0], qh[s][1], qh[s][2], qh[s][3], x0.x, x0.y);
        mma16(S1, qh[s][0], qh[s][1], qh[s][2], qh[s][3], x1.x, x1.y);
      }
      float p00 = __expf(S0[0]);
      float p01 = __expf(S0[1]);
      float p02 = __expf(S0[2]);
      float p03 = __expf(S0[3]);
      float p10 = __expf(S1[0]);
      float p11 = __expf(S1[1]);
      float p12 = __expf(S1[2]);
      float p13 = __expf(S1[3]);
      l0 += p00 + p01 + p10 + p11;
      l1 += p02 + p03 + p12 + p13;
      uint32_t pa0 = h2(p00, p01);
      uint32_t pa1 = h2(p02, p03);
      uint32_t pa2 = h2(p10, p11);
      uint32_t pa3 = h2(p12, p13);
#pragma unroll
      for (int v = 0; v < 5; v++) {
        uint2 bb = *(const uint2*)(Vb + ((np * 40 + 8 * v + rg) * 4 + q) * 2);
        mma16(O[v], pa0, pa1, pa2, pa3, bb.x, bb.y);
      }
    }

    if (kt < N_SEQ / 64 - 1) {
      uint32_t* kd = &Ks[buf ^ 1][0];
      uint16_t* vd = (uint16_t*)&Vs[buf ^ 1][0];
#pragma unroll
      for (int it = 0; it < 3; it++)
        if (act[it]) {
          kd[koff0[it]] = h2(kr[it].x, kr[it].y);
          kd[koff1[it]] = h2(kr[it].z, kr[it].w);
          vd[v16[it] + 0] = __half_as_ushort(__float2half_rn(vr[it].x));
          vd[v16[it] + 16] = __half_as_ushort(__float2half_rn(vr[it].y));
          vd[v16[it] + 32] = __half_as_ushort(__float2half_rn(vr[it].z));
          vd[v16[it] + 48] = __half_as_ushort(__float2half_rn(vr[it].w));
        }
    }
    __syncthreads();
  }

  l0 += __shfl_xor_sync(0xffffffffu, l0, 1);
  l0 += __shfl_xor_sync(0xffffffffu, l0, 2);
  l1 += __shfl_xor_sync(0xffffffffu, l1, 1);
  l1 += __shfl_xor_sync(0xffffffffu, l1, 2);
  float inv0 = 1.f / l0, inv1 = 1.f / l1;

  const int row = q0 + wid * 16 + rg;
  float* ob0 = Oa + (size_t)(b * N_SEQ + row) * E_DIM + h * D_HEAD;
  float* ob1 = Oa + (size_t)(b * N_SEQ + row + 8) * E_DIM + h * D_HEAD;
#pragma unroll
  for (int v = 0; v < 5; v++) {
    int col = 8 * v + 2 * q;
    if (col < 36) {
      *(float2*)(ob0 + col) = make_float2(O[v][0] * inv0, O[v][1] * inv0);
      *(float2*)(ob1 + col) = make_float2(O[v][2] * inv1, O[v][3] * inv1);
    }
  }
}

// ---------------------------------------------------------------------------
// GEMM body (unchanged from R13): single-term tf32, 3-stage cp.async pipeline.
// ---------------------------------------------------------------------------
#define NKT (E_DIM / 16)  // 18

__device__ __forceinline__ void gemm_body(const float* __restrict__ A,
                                          const float* __restrict__ W,
                                          const float* __restrict__ bias,
                                          float* __restrict__ C, float scale,
                                          int row_blk, int col_blk) {
  __shared__ float Wsm[3][16][104];
  __shared__ float As[3][64][20];

  const int t = threadIdx.x;
  const int wid = t >> 5;
  const int lane = t & 31;
  const int q = lane & 3;
  const int rg = lane >> 2;
  const int warp_m = wid & 1;
  const int warp_n = wid >> 1;
  const int ncol0 = warp_n * 48;

  int wg_off[3], ws_off[3];
#pragma unroll
  for (int i = 0; i < 3; i++) {
    int idx = t + i * 128;
    int kk = idx / 24, n4 = idx - kk * 24;
    wg_off[i] = kk * E_DIM + n4 * 4;
    ws_off[i] = kk * 104 + n4 * 4;
  }
  int ag_off[2], as_off[2];
#pragma unroll
  for (int i = 0; i < 2; i++) {
    int idx = t + i * 128;
    int row = idx >> 2, k4 = idx & 3;
    ag_off[i] = row * E_DIM + k4 * 4;
    as_off[i] = row * 20 + k4 * 4;
  }
  const float* Wg = W + col_blk;
  const float* Ag = A + (size_t)row_blk * E_DIM;
  const uint32_t wbase = (uint32_t)__cvta_generic_to_shared(&Wsm[0][0][0]);
  const uint32_t abase = (uint32_t)__cvta_generic_to_shared(&As[0][0][0]);

  float acc[2][6][4];
#pragma unroll
  for (int mb = 0; mb < 2; mb++)
#pragma unroll
    for (int nb = 0; nb < 6; nb++)
#pragma unroll
      for (int i = 0; i < 4; i++) acc[mb][nb][i] = 0.f;

#pragma unroll
  for (int st = 0; st < 3; st++) {
    const int k0 = st * 16;
#pragma unroll
    for (int i = 0; i < 3; i++)
      CP_ASYNC16(wbase + (uint32_t)(st * 16 * 104 + ws_off[i]) * 4u,
                 Wg + (size_t)k0 * E_DIM + wg_off[i]);
#pragma unroll
    for (int i = 0; i < 2; i++)
      CP_ASYNC16(abase + (uint32_t)(st * 64 * 20 + as_off[i]) * 4u,
                 Ag + k0 + ag_off[i]);
    CP_COMMIT();
  }

  for (int kt = 0; kt < NKT; kt++) {
    if (kt < NKT - 2) {
      CP_WAIT(2);
    } else if (kt == NKT - 2) {
      CP_WAIT(1);
    } else {
      CP_WAIT(0);
    }
    __syncthreads();

    const int buf = kt % 3;
    const float* Wb = &Wsm[buf][0][0];
    const float* Ab = &As[buf][0][0];
#pragma unroll
    for (int s = 0; s < 2; s++) {
      uint32_t ah[2][4];
#pragma unroll
      for (int mb = 0; mb < 2; mb++) {
        const int r0 = warp_m * 32 + mb * 16;
        ah[mb][0] = f2tf(Ab[(r0 + rg) * 20 + 8 * s + q]);
        ah[mb][1] = f2tf(Ab[(r0 + rg + 8) * 20 + 8 * s + q]);
        ah[mb][2] = f2tf(Ab[(r0 + rg) * 20 + 8 * s + q + 4]);
        ah[mb][3] = f2tf(Ab[(r0 + rg + 8) * 20 + 8 * s + q + 4]);
      }
#pragma unroll
      for (int nb = 0; nb < 6; nb++) {
        const int n = ncol0 + nb * 8 + rg;
        uint32_t bh0 = f2tf(Wb[(8 * s + q) * 104 + n]);
        uint32_t bh1 = f2tf(Wb[(8 * s + q + 4) * 104 + n]);
#pragma unroll
        for (int mb = 0; mb < 2; mb++) {
          mma8(acc[mb][nb], ah[mb][0], ah[mb][1], ah[mb][2], ah[mb][3], bh0, bh1);
        }
      }
    }
    __syncthreads();

    if (kt + 3 < NKT) {
      const int k0 = (kt + 3) * 16;
#pragma unroll
      for (int i = 0; i < 3; i++)
        CP_ASYNC16(wbase + (uint32_t)(buf * 16 * 104 + ws_off[i]) * 4u,
                   Wg + (size_t)k0 * E_DIM + wg_off[i]);
#pragma unroll
      for (int i = 0; i < 2; i++)
        CP_ASYNC16(abase + (uint32_t)(buf * 64 * 20 + as_off[i]) * 4u,
                   Ag + k0 + ag_off[i]);
      CP_COMMIT();
    }
  }

#pragma unroll
  for (int mb = 0; mb < 2; mb++) {
    const int r0 = row_blk + warp_m * 32 + mb * 16 + rg;
#pragma unroll
    for (int nb = 0; nb < 6; nb++) {
      const int c = col_blk + ncol0 + nb * 8 + 2 * q;
      const float b0 = bias[c], b1 = bias[c + 1];
      *(float2*)(C + (size_t)r0 * E_DIM + c) =
          make_float2((acc[mb][nb][0] + b0) * scale,
                      (acc[mb][nb][1] + b1) * scale);
      *(float2*)(C + (size_t)(r0 + 8) * E_DIM + c) =
          make_float2((acc[mb][nb][2] + b0) * scale,
                      (acc[mb][nb][3] + b1) * scale);
    }
  }
}

__global__ __launch_bounds__(128, 6) void gemm_qkv_kernel(
    const float* __restrict__ Aq, const float* __restrict__ Ak,
    const float* __restrict__ Av, const float* __restrict__ Wq,
    const float* __restrict__ Wk, const float* __restrict__ Wv,
    const float* __restrict__ bq, const float* __restrict__ bk,
    const float* __restrict__ bv, float* __restrict__ Cq,
    float* __restrict__ Ck, float* __restrict__ Cv, float scaling) {
  const int z = blockIdx.z;
  const float* A = (z == 0) ? Aq : (z == 1) ? Ak : Av;
  const float* W = (z == 0) ? Wq : (z == 1) ? Wk : Wv;
  const float* bias = (z == 0) ? bq : (z == 1) ? bk : bv;
  float* C = (z == 0) ? Cq : (z == 1) ? Ck : Cv;
  const float scale = (z == 0) ? scaling : 1.0f;
  gemm_body(A, W, bias, C, scale, blockIdx.y * 64, blockIdx.x * 96);
}

__global__ __launch_bounds__(128, 6) void gemm_mma_kernel(
    const float* __restrict__ A, const float* __restrict__ W,
    const float* __restrict__ bias, float* __restrict__ C, float scale) {
  gemm_body(A, W, bias, C, scale, blockIdx.y * 64, blockIdx.x * 96);
}

// ---------------------------------------------------------------------------
extern "C" void kernel_launch(void* const* d_in, const int* in_sizes, int n_in,
                              void* d_out, int out_size) {
  const float* query = (const float*)d_in[0];
  const float* key   = (const float*)d_in[1];
  const float* value = (const float*)d_in[2];
  const float* Wq = (const float*)d_in[3];
  const float* bq = (const float*)d_in[4];
  const float* Wk = (const float*)d_in[5];
  const float* bk = (const float*)d_in[6];
  const float* Wv = (const float*)d_in[7];
  const float* bv = (const float*)d_in[8];
  const float* Wo = (const float*)d_in[9];
  const float* bo = (const float*)d_in[10];
  float* out = (float*)d_out;

  float *gq, *gk, *gv, *ga;
  cudaGetSymbolAddress((void**)&gq, g_q);
  cudaGetSymbolAddress((void**)&gk, g_k);
  cudaGetSymbolAddress((void**)&gv, g_v);
  cudaGetSymbolAddress((void**)&ga, g_att);

  const float scaling = 1.0f / 6.0f;  // D=36 -> 36^-0.5
  dim3 qkvGrid(E_DIM / 96, M_ROWS / 64, 3);
  dim3 gGrid(E_DIM / 96, M_ROWS / 64);
  dim3 gBlk(128);

  gemm_qkv_kernel<<<qkvGrid, gBlk>>>(query, key, value, Wq, Wk, Wv, bq, bk, bv,
                                     gq, gk, gv, scaling);

  attn_mma_kernel<<<dim3(N_SEQ / 128, B_SZ * H_NUM), 256>>>(gq, gk, gv, ga);

  gemm_mma_kernel<<<gGrid, gBlk>>>(ga, Wo, bo, out, 1.0f);
}